// round 1
// baseline (speedup 1.0000x reference)
#include <cuda_runtime.h>
#include <cuda_bf16.h>
#include <math.h>

// Problem constants
#define E_   2048
#define H_   16
#define D_   128
#define B_   4
#define T_   1024
#define TP_  3072
#define S_   (TP_ + T_)      // 4096
#define NTOK (B_ * T_)       // 4096

// Scratch (device globals -- no allocations allowed)
__device__ float g_q[NTOK * E_];
__device__ float g_k[NTOK * E_];
__device__ float g_v[NTOK * E_];
__device__ float g_attn[NTOK * E_];

// ---------------------------------------------------------------------------
// GEMM:  C[n,m] = sum_k A[n,k] * W[m,k] + bias[m]
// A: [N,K] row-major, W: [M,K] row-major (torch Linear weight), C: [N,M]
// Tiles: 128x128x16, 256 threads, 8x8 microtile per thread.
// ---------------------------------------------------------------------------
#define BM 128
#define BN 128
#define BK 16

__global__ __launch_bounds__(256, 2) void gemm_nt_bias(
    const float* __restrict__ A, const float* __restrict__ W,
    const float* __restrict__ bias, float* __restrict__ C,
    int N, int M, int K)
{
    __shared__ float As[BK][BM + 4];
    __shared__ float Ws[BK][BN + 4];

    const int brow = blockIdx.y * BM;
    const int bcol = blockIdx.x * BN;
    const int tid  = threadIdx.x;
    const int tx   = tid & 15;
    const int ty   = tid >> 4;

    float acc[8][8];
#pragma unroll
    for (int i = 0; i < 8; i++)
#pragma unroll
        for (int j = 0; j < 8; j++) acc[i][j] = 0.f;

    for (int k0 = 0; k0 < K; k0 += BK) {
#pragma unroll
        for (int l = 0; l < 2; l++) {
            int i = tid + l * 256;        // 0..511
            int r = i >> 2;               // 0..127
            int c = (i & 3) << 2;         // 0,4,8,12
            float4 av = *(const float4*)&A[(size_t)(brow + r) * K + k0 + c];
            As[c + 0][r] = av.x; As[c + 1][r] = av.y;
            As[c + 2][r] = av.z; As[c + 3][r] = av.w;
            float4 wv = *(const float4*)&W[(size_t)(bcol + r) * K + k0 + c];
            Ws[c + 0][r] = wv.x; Ws[c + 1][r] = wv.y;
            Ws[c + 2][r] = wv.z; Ws[c + 3][r] = wv.w;
        }
        __syncthreads();

#pragma unroll
        for (int kk = 0; kk < BK; kk++) {
            float a[8], b[8];
            *(float4*)&a[0] = *(const float4*)&As[kk][ty * 8];
            *(float4*)&a[4] = *(const float4*)&As[kk][ty * 8 + 4];
            *(float4*)&b[0] = *(const float4*)&Ws[kk][tx * 8];
            *(float4*)&b[4] = *(const float4*)&Ws[kk][tx * 8 + 4];
#pragma unroll
            for (int i = 0; i < 8; i++)
#pragma unroll
                for (int j = 0; j < 8; j++)
                    acc[i][j] = fmaf(a[i], b[j], acc[i][j]);
        }
        __syncthreads();
    }

    // epilogue
#pragma unroll
    for (int i = 0; i < 8; i++) {
        size_t row = (size_t)(brow + ty * 8 + i);
        float4 o0, o1;
        o0.x = acc[i][0] + bias[bcol + tx * 8 + 0];
        o0.y = acc[i][1] + bias[bcol + tx * 8 + 1];
        o0.z = acc[i][2] + bias[bcol + tx * 8 + 2];
        o0.w = acc[i][3] + bias[bcol + tx * 8 + 3];
        o1.x = acc[i][4] + bias[bcol + tx * 8 + 4];
        o1.y = acc[i][5] + bias[bcol + tx * 8 + 5];
        o1.z = acc[i][6] + bias[bcol + tx * 8 + 6];
        o1.w = acc[i][7] + bias[bcol + tx * 8 + 7];
        *(float4*)&C[row * M + bcol + tx * 8]     = o0;
        *(float4*)&C[row * M + bcol + tx * 8 + 4] = o1;
    }
}

// ---------------------------------------------------------------------------
// Scatter new K/V rows (row-major [NTOK,E]) into cache [B,H,S,D] at [TP, S)
// ---------------------------------------------------------------------------
__global__ void scatter_kv(const float* __restrict__ krm,
                           const float* __restrict__ vrm,
                           float* __restrict__ kc, float* __restrict__ vc)
{
    int idx = blockIdx.x * blockDim.x + threadIdx.x;   // float4 index
    const int total4 = NTOK * E_ / 4;
    if (idx >= total4) return;
    int n  = idx / (E_ / 4);
    int m4 = (idx % (E_ / 4)) * 4;
    int b = n / T_, t = n % T_;
    int h = m4 / D_, d = m4 % D_;
    size_t dst = ((size_t)(b * H_ + h) * S_ + TP_ + t) * D_ + d;
    *(float4*)&kc[dst] = *(const float4*)&krm[(size_t)n * E_ + m4];
    *(float4*)&vc[dst] = *(const float4*)&vrm[(size_t)n * E_ + m4];
}

// ---------------------------------------------------------------------------
// Copy past_k/past_v [B,H,TP,D] into cache positions [0, TP)
// ---------------------------------------------------------------------------
__global__ void copy_past(const float* __restrict__ pk,
                          const float* __restrict__ pv,
                          float* __restrict__ kc, float* __restrict__ vc)
{
    int idx = blockIdx.x * blockDim.x + threadIdx.x;   // float4 index
    const int total4 = B_ * H_ * TP_ * D_ / 4;
    if (idx >= total4) return;
    int bh  = idx / (TP_ * D_ / 4);
    int off = (idx % (TP_ * D_ / 4)) * 4;
    size_t dst = (size_t)bh * S_ * D_ + off;
    *(float4*)&kc[dst] = *(const float4*)&pk[(size_t)idx * 4];
    *(float4*)&vc[dst] = *(const float4*)&pv[(size_t)idx * 4];
}

// ---------------------------------------------------------------------------
// Flash attention, fp32. CTA = (qtile=64 rows, head, batch). 256 threads.
// Chunks of 64 keys. K and V share one smem buffer (sequential phases).
// Thread grid 16x16: scores 4 rows x 4 interleaved cols; PV 4 rows x 8 cols.
// ---------------------------------------------------------------------------
#define QT 64
#define CH 64
#define QPITCH 132
#define PPITCH 68

__global__ __launch_bounds__(256) void attn_kernel(
    const float* __restrict__ kcache, const float* __restrict__ vcache)
{
    extern __shared__ float sm[];
    float* sQ     = sm;                        // QT x 132
    float* sKV    = sQ  + QT * QPITCH;         // CH x 132
    float* sP     = sKV + CH * QPITCH;         // QT x 68
    float* sRed   = sP  + QT * PPITCH;         // QT x 16
    float* sM     = sRed + QT * 16;            // QT
    float* sL     = sM + QT;                   // QT
    float* sAlpha = sL + QT;                   // QT

    const int qt = blockIdx.x, h = blockIdx.y, b = blockIdx.z;
    const int tid = threadIdx.x;
    const int tx = tid & 15, ty = tid >> 4;
    const float scale = 0.08838834764831845f;  // 1/sqrt(128)

    // Load Q tile (scaled)
    for (int i = tid; i < QT * D_ / 4; i += 256) {
        int r  = i / (D_ / 4);
        int c4 = (i % (D_ / 4)) * 4;
        float4 qv = *(const float4*)&g_q[(size_t)(b * T_ + qt * QT + r) * E_ + h * D_ + c4];
        qv.x *= scale; qv.y *= scale; qv.z *= scale; qv.w *= scale;
        *(float4*)&sQ[r * QPITCH + c4] = qv;
    }
    if (tid < QT) { sM[tid] = -1e30f; sL[tid] = 0.f; }

    float acc[4][8];
#pragma unroll
    for (int i = 0; i < 4; i++)
#pragma unroll
        for (int j = 0; j < 8; j++) acc[i][j] = 0.f;

    const float* kbase = kcache + (size_t)(b * H_ + h) * S_ * D_;
    const float* vbase = vcache + (size_t)(b * H_ + h) * S_ * D_;

    for (int s0 = 0; s0 < S_; s0 += CH) {
        __syncthreads();
        // load K chunk
        for (int i = tid; i < CH * D_ / 4; i += 256) {
            int r  = i / (D_ / 4);
            int c4 = (i % (D_ / 4)) * 4;
            *(float4*)&sKV[r * QPITCH + c4] =
                *(const float4*)&kbase[(size_t)(s0 + r) * D_ + c4];
        }
        __syncthreads();

        // scores: rows ty*4+i, cols tx + 16*j
        float s[4][4];
#pragma unroll
        for (int i = 0; i < 4; i++)
#pragma unroll
            for (int j = 0; j < 4; j++) s[i][j] = 0.f;

#pragma unroll 4
        for (int d4 = 0; d4 < D_; d4 += 4) {
            float4 q[4], k[4];
#pragma unroll
            for (int i = 0; i < 4; i++)
                q[i] = *(const float4*)&sQ[(ty * 4 + i) * QPITCH + d4];
#pragma unroll
            for (int j = 0; j < 4; j++)
                k[j] = *(const float4*)&sKV[(tx + 16 * j) * QPITCH + d4];
#pragma unroll
            for (int i = 0; i < 4; i++)
#pragma unroll
                for (int j = 0; j < 4; j++) {
                    s[i][j] = fmaf(q[i].x, k[j].x, s[i][j]);
                    s[i][j] = fmaf(q[i].y, k[j].y, s[i][j]);
                    s[i][j] = fmaf(q[i].z, k[j].z, s[i][j]);
                    s[i][j] = fmaf(q[i].w, k[j].w, s[i][j]);
                }
        }

        // row max (partial per thread -> smem reduce)
#pragma unroll
        for (int i = 0; i < 4; i++) {
            float tm = fmaxf(fmaxf(s[i][0], s[i][1]), fmaxf(s[i][2], s[i][3]));
            sRed[(ty * 4 + i) * 16 + tx] = tm;
        }
        __syncthreads();
        if (tid < QT) {
            float mx = sRed[tid * 16];
#pragma unroll
            for (int t = 1; t < 16; t++) mx = fmaxf(mx, sRed[tid * 16 + t]);
            float mo = sM[tid];
            float mn = fmaxf(mo, mx);
            sM[tid] = mn;
            float al = __expf(mo - mn);
            sAlpha[tid] = al;
            sL[tid] *= al;
        }
        __syncthreads();

        // P = exp(s - m), write smem; partial rowsum; rescale acc
        float rsum[4];
#pragma unroll
        for (int i = 0; i < 4; i++) {
            float mn = sM[ty * 4 + i];
            rsum[i] = 0.f;
#pragma unroll
            for (int j = 0; j < 4; j++) {
                float p = __expf(s[i][j] - mn);
                sP[(ty * 4 + i) * PPITCH + tx + 16 * j] = p;
                rsum[i] += p;
            }
            sRed[(ty * 4 + i) * 16 + tx] = rsum[i];
            float al = sAlpha[ty * 4 + i];
#pragma unroll
            for (int j = 0; j < 8; j++) acc[i][j] *= al;
        }
        __syncthreads();
        if (tid < QT) {
            float sum = 0.f;
#pragma unroll
            for (int t = 0; t < 16; t++) sum += sRed[tid * 16 + t];
            sL[tid] += sum;
        }
        // load V chunk into shared KV buffer (K no longer needed)
        for (int i = tid; i < CH * D_ / 4; i += 256) {
            int r  = i / (D_ / 4);
            int c4 = (i % (D_ / 4)) * 4;
            *(float4*)&sKV[r * QPITCH + c4] =
                *(const float4*)&vbase[(size_t)(s0 + r) * D_ + c4];
        }
        __syncthreads();

        // PV: acc[i][j] += P[row][kk] * V[kk][tx*8+j]
#pragma unroll 8
        for (int kk = 0; kk < CH; kk++) {
            float p[4];
#pragma unroll
            for (int i = 0; i < 4; i++) p[i] = sP[(ty * 4 + i) * PPITCH + kk];
            float4 v0 = *(const float4*)&sKV[kk * QPITCH + tx * 8];
            float4 v1 = *(const float4*)&sKV[kk * QPITCH + tx * 8 + 4];
#pragma unroll
            for (int i = 0; i < 4; i++) {
                acc[i][0] = fmaf(p[i], v0.x, acc[i][0]);
                acc[i][1] = fmaf(p[i], v0.y, acc[i][1]);
                acc[i][2] = fmaf(p[i], v0.z, acc[i][2]);
                acc[i][3] = fmaf(p[i], v0.w, acc[i][3]);
                acc[i][4] = fmaf(p[i], v1.x, acc[i][4]);
                acc[i][5] = fmaf(p[i], v1.y, acc[i][5]);
                acc[i][6] = fmaf(p[i], v1.z, acc[i][6]);
                acc[i][7] = fmaf(p[i], v1.w, acc[i][7]);
            }
        }
    }

    __syncthreads();
    // epilogue: normalize by l, write to g_attn row-major [NTOK, E]
#pragma unroll
    for (int i = 0; i < 4; i++) {
        int rlocal = ty * 4 + i;
        float inv = 1.0f / sL[rlocal];
        int rglob = qt * QT + rlocal;
        float4 o0, o1;
        o0.x = acc[i][0] * inv; o0.y = acc[i][1] * inv;
        o0.z = acc[i][2] * inv; o0.w = acc[i][3] * inv;
        o1.x = acc[i][4] * inv; o1.y = acc[i][5] * inv;
        o1.z = acc[i][6] * inv; o1.w = acc[i][7] * inv;
        size_t base = (size_t)(b * T_ + rglob) * E_ + h * D_ + tx * 8;
        *(float4*)&g_attn[base]     = o0;
        *(float4*)&g_attn[base + 4] = o1;
    }
}

// ---------------------------------------------------------------------------
extern "C" void kernel_launch(void* const* d_in, const int* in_sizes, int n_in,
                              void* d_out, int out_size)
{
    const float* x      = (const float*)d_in[0];
    const float* past_k = (const float*)d_in[1];
    const float* past_v = (const float*)d_in[2];
    const float* Wq     = (const float*)d_in[3];
    const float* bq     = (const float*)d_in[4];
    const float* Wk     = (const float*)d_in[5];
    const float* bk     = (const float*)d_in[6];
    const float* Wv     = (const float*)d_in[7];
    const float* bv     = (const float*)d_in[8];
    const float* Wo     = (const float*)d_in[9];
    const float* bo     = (const float*)d_in[10];

    float* out = (float*)d_out;                       // [B,T,E]
    float* kc  = out + (size_t)NTOK * E_;             // [B,H,S,D]
    float* vc  = kc + (size_t)B_ * H_ * S_ * D_;      // [B,H,S,D]

    void *pq, *pk, *pv, *pattn;
    cudaGetSymbolAddress(&pq, g_q);
    cudaGetSymbolAddress(&pk, g_k);
    cudaGetSymbolAddress(&pv, g_v);
    cudaGetSymbolAddress(&pattn, g_attn);

    dim3 gg(E_ / BN, NTOK / BM);   // (16, 32)
    gemm_nt_bias<<<gg, 256>>>(x, Wq, bq, (float*)pq, NTOK, E_, E_);
    gemm_nt_bias<<<gg, 256>>>(x, Wk, bk, (float*)pk, NTOK, E_, E_);
    gemm_nt_bias<<<gg, 256>>>(x, Wv, bv, (float*)pv, NTOK, E_, E_);

    {
        int total4 = NTOK * E_ / 4;
        scatter_kv<<<(total4 + 255) / 256, 256>>>((const float*)pk, (const float*)pv, kc, vc);
    }
    {
        int total4 = B_ * H_ * TP_ * D_ / 4;
        copy_past<<<(total4 + 255) / 256, 256>>>(past_k, past_v, kc, vc);
    }

    // attention
    size_t smem = (size_t)(QT * QPITCH + CH * QPITCH + QT * PPITCH + QT * 16 + 3 * QT) * sizeof(float);
    cudaFuncSetAttribute(attn_kernel, cudaFuncAttributeMaxDynamicSharedMemorySize, (int)smem);
    attn_kernel<<<dim3(T_ / QT, H_, B_), 256, smem>>>(kc, vc);

    // output projection
    gemm_nt_bias<<<gg, 256>>>((const float*)pattn, Wo, bo, out, NTOK, E_, E_);
}

// round 2
// speedup vs baseline: 2.7920x; 2.7920x over previous
#include <cuda_runtime.h>
#include <cuda_bf16.h>
#include <math.h>

// Problem constants
#define E_   2048
#define H_   16
#define D_   128
#define B_   4
#define T_   1024
#define TP_  3072
#define S_   (TP_ + T_)      // 4096
#define NTOK (B_ * T_)       // 4096

// Scratch (device globals -- no allocations allowed)
__device__ float g_q[NTOK * E_];
__device__ float g_k[NTOK * E_];
__device__ float g_v[NTOK * E_];
__device__ float g_attn[NTOK * E_];

// ---------------------------------------------------------------------------
// Helpers: tf32 convert + mma.sync m16n8k8 tf32
// ---------------------------------------------------------------------------
__device__ __forceinline__ unsigned f2tf32(float f) {
    unsigned u;
    asm("cvt.rna.tf32.f32 %0, %1;" : "=r"(u) : "f"(f));
    return u;
}

__device__ __forceinline__ void mma_tf32(float c[4],
    unsigned a0, unsigned a1, unsigned a2, unsigned a3,
    unsigned b0, unsigned b1)
{
    asm volatile(
        "mma.sync.aligned.m16n8k8.row.col.f32.tf32.tf32.f32 "
        "{%0,%1,%2,%3}, {%4,%5,%6,%7}, {%8,%9}, {%0,%1,%2,%3};"
        : "+f"(c[0]), "+f"(c[1]), "+f"(c[2]), "+f"(c[3])
        : "r"(a0), "r"(a1), "r"(a2), "r"(a3), "r"(b0), "r"(b1));
}

// ---------------------------------------------------------------------------
// Tensor-core GEMM: C[n,m] = A[n,:] . W[m,:] + bias[m]
// A:[4096,2048] rm, W:[2048,2048] rm, C:[4096,2048]
// Block 128x128x32, 8 warps (4 rows x 2 cols), warp tile 32x64.
// Register-staged pipeline: LDG of next K-tile overlaps MMA of current.
// ---------------------------------------------------------------------------
#define GP 36   // smem pitch (conflict-free fragment loads)

__global__ __launch_bounds__(256, 2) void gemm_tc(
    const float* __restrict__ A, const float* __restrict__ W,
    const float* __restrict__ bias, float* __restrict__ C)
{
    __shared__ unsigned sA[128 * GP];
    __shared__ unsigned sB[128 * GP];

    const int tid  = threadIdx.x;
    const int lane = tid & 31, wid = tid >> 5;
    const int wm = wid >> 1, wn = wid & 1;       // 4x2 warp grid
    const int g = lane >> 2, t = lane & 3;
    const int brow = blockIdx.y * 128, bcol = blockIdx.x * 128;

    float acc[2][8][4];
#pragma unroll
    for (int mi = 0; mi < 2; mi++)
#pragma unroll
        for (int nj = 0; nj < 8; nj++)
#pragma unroll
            for (int q = 0; q < 4; q++) acc[mi][nj][q] = 0.f;

    float4 ra[4], rb[4];
    // prologue load (k0 = 0)
#pragma unroll
    for (int l = 0; l < 4; l++) {
        int i = tid + l * 256;
        int r = i >> 3, c = (i & 7) * 4;
        ra[l] = *(const float4*)&A[(size_t)(brow + r) * E_ + c];
        rb[l] = *(const float4*)&W[(size_t)(bcol + r) * E_ + c];
    }

    for (int k0 = 0; k0 < E_; k0 += 32) {
        // store staged tile (tf32 rounding)
#pragma unroll
        for (int l = 0; l < 4; l++) {
            int i = tid + l * 256;
            int r = i >> 3, c = (i & 7) * 4;
            sA[r * GP + c + 0] = f2tf32(ra[l].x);
            sA[r * GP + c + 1] = f2tf32(ra[l].y);
            sA[r * GP + c + 2] = f2tf32(ra[l].z);
            sA[r * GP + c + 3] = f2tf32(ra[l].w);
            sB[r * GP + c + 0] = f2tf32(rb[l].x);
            sB[r * GP + c + 1] = f2tf32(rb[l].y);
            sB[r * GP + c + 2] = f2tf32(rb[l].z);
            sB[r * GP + c + 3] = f2tf32(rb[l].w);
        }
        __syncthreads();

        // prefetch next tile into registers
        if (k0 + 32 < E_) {
#pragma unroll
            for (int l = 0; l < 4; l++) {
                int i = tid + l * 256;
                int r = i >> 3, c = (i & 7) * 4;
                ra[l] = *(const float4*)&A[(size_t)(brow + r) * E_ + k0 + 32 + c];
                rb[l] = *(const float4*)&W[(size_t)(bcol + r) * E_ + k0 + 32 + c];
            }
        }

        // MMA over 4 k-steps
#pragma unroll
        for (int ks = 0; ks < 4; ks++) {
            unsigned a[2][4];
#pragma unroll
            for (int mi = 0; mi < 2; mi++) {
                int r = wm * 32 + mi * 16 + g;
                a[mi][0] = sA[r * GP + ks * 8 + t];
                a[mi][1] = sA[(r + 8) * GP + ks * 8 + t];
                a[mi][2] = sA[r * GP + ks * 8 + t + 4];
                a[mi][3] = sA[(r + 8) * GP + ks * 8 + t + 4];
            }
#pragma unroll
            for (int nj = 0; nj < 8; nj++) {
                int n = wn * 64 + nj * 8 + g;
                unsigned b0 = sB[n * GP + ks * 8 + t];
                unsigned b1 = sB[n * GP + ks * 8 + t + 4];
                mma_tf32(acc[0][nj], a[0][0], a[0][1], a[0][2], a[0][3], b0, b1);
                mma_tf32(acc[1][nj], a[1][0], a[1][1], a[1][2], a[1][3], b0, b1);
            }
        }
        __syncthreads();
    }

    // epilogue with bias
#pragma unroll
    for (int mi = 0; mi < 2; mi++) {
#pragma unroll
        for (int nj = 0; nj < 8; nj++) {
            int row = brow + wm * 32 + mi * 16 + g;
            int col = bcol + wn * 64 + nj * 8 + t * 2;
            float b0 = bias[col], b1 = bias[col + 1];
            float2 v0 = { acc[mi][nj][0] + b0, acc[mi][nj][1] + b1 };
            float2 v1 = { acc[mi][nj][2] + b0, acc[mi][nj][3] + b1 };
            *(float2*)&C[(size_t)row * E_ + col]       = v0;
            *(float2*)&C[(size_t)(row + 8) * E_ + col] = v1;
        }
    }
}

// ---------------------------------------------------------------------------
// Scatter new K/V rows (row-major [NTOK,E]) into cache [B,H,S,D] at [TP, S)
// ---------------------------------------------------------------------------
__global__ void scatter_kv(const float* __restrict__ krm,
                           const float* __restrict__ vrm,
                           float* __restrict__ kc, float* __restrict__ vc)
{
    int idx = blockIdx.x * blockDim.x + threadIdx.x;   // float4 index
    const int total4 = NTOK * E_ / 4;
    if (idx >= total4) return;
    int n  = idx / (E_ / 4);
    int m4 = (idx % (E_ / 4)) * 4;
    int b = n / T_, tt = n % T_;
    int h = m4 / D_, d = m4 % D_;
    size_t dst = ((size_t)(b * H_ + h) * S_ + TP_ + tt) * D_ + d;
    *(float4*)&kc[dst] = *(const float4*)&krm[(size_t)n * E_ + m4];
    *(float4*)&vc[dst] = *(const float4*)&vrm[(size_t)n * E_ + m4];
}

__global__ void copy_past(const float* __restrict__ pk,
                          const float* __restrict__ pv,
                          float* __restrict__ kc, float* __restrict__ vc)
{
    int idx = blockIdx.x * blockDim.x + threadIdx.x;   // float4 index
    const int total4 = B_ * H_ * TP_ * D_ / 4;
    if (idx >= total4) return;
    int bh  = idx / (TP_ * D_ / 4);
    int off = (idx % (TP_ * D_ / 4)) * 4;
    size_t dst = (size_t)bh * S_ * D_ + off;
    *(float4*)&kc[dst] = *(const float4*)&pk[(size_t)idx * 4];
    *(float4*)&vc[dst] = *(const float4*)&pv[(size_t)idx * 4];
}

// ---------------------------------------------------------------------------
// Tensor-core flash attention. CTA = (qtile 128 rows, h, b). 256 thr, 8 warps.
// Warp w owns q rows [w*16, w*16+16). Chunks of 64 keys.
// Q in smem (tf32, reused across all chunks); K/V share one smem buffer.
// P routed through smem as tf32 for the PV mma.
// ---------------------------------------------------------------------------
#define QP  132
#define KVP 136
#define PP  68

__global__ __launch_bounds__(256) void attn_tc(
    const float* __restrict__ kcache, const float* __restrict__ vcache)
{
    extern __shared__ unsigned smu[];
    unsigned* sQ  = smu;                 // 128 x 132
    unsigned* sKV = sQ + 128 * QP;       // 64 x 136
    unsigned* sP  = sKV + 64 * KVP;      // 128 x 68

    const int qt = blockIdx.x, h = blockIdx.y, b = blockIdx.z;
    const int tid = threadIdx.x, lane = tid & 31, w = tid >> 5;
    const int g = lane >> 2, t = lane & 3;
    const float scale = 0.08838834764831845f;  // 1/sqrt(128)

    // Load Q tile (scaled, tf32)
#pragma unroll
    for (int l = 0; l < 16; l++) {
        int i = tid + l * 256;
        int r = i >> 5, c = (i & 31) * 4;
        float4 qv = *(const float4*)&g_q[(size_t)(b * T_ + qt * 128 + r) * E_ + h * D_ + c];
        sQ[r * QP + c + 0] = f2tf32(qv.x * scale);
        sQ[r * QP + c + 1] = f2tf32(qv.y * scale);
        sQ[r * QP + c + 2] = f2tf32(qv.z * scale);
        sQ[r * QP + c + 3] = f2tf32(qv.w * scale);
    }

    float m0 = -1e30f, m1 = -1e30f, l0 = 0.f, l1 = 0.f;
    float acc_o[16][4];
#pragma unroll
    for (int nj = 0; nj < 16; nj++)
#pragma unroll
        for (int q = 0; q < 4; q++) acc_o[nj][q] = 0.f;

    const float* kb = kcache + (size_t)(b * H_ + h) * S_ * D_;
    const float* vb = vcache + (size_t)(b * H_ + h) * S_ * D_;

    __syncthreads();

    for (int s0 = 0; s0 < S_; s0 += 64) {
        // load K chunk (64 x 128)
#pragma unroll
        for (int l = 0; l < 8; l++) {
            int i = tid + l * 256;
            int r = i >> 5, c = (i & 31) * 4;
            float4 kv = *(const float4*)&kb[(size_t)(s0 + r) * D_ + c];
            sKV[r * KVP + c + 0] = f2tf32(kv.x);
            sKV[r * KVP + c + 1] = f2tf32(kv.y);
            sKV[r * KVP + c + 2] = f2tf32(kv.z);
            sKV[r * KVP + c + 3] = f2tf32(kv.w);
        }
        __syncthreads();

        // S = Q K^T   (warp: 16 q-rows x 64 keys)
        float accs[8][4];
#pragma unroll
        for (int nj = 0; nj < 8; nj++)
#pragma unroll
            for (int q = 0; q < 4; q++) accs[nj][q] = 0.f;

#pragma unroll
        for (int ks = 0; ks < 16; ks++) {
            int r = w * 16 + g;
            unsigned a0 = sQ[r * QP + ks * 8 + t];
            unsigned a1 = sQ[(r + 8) * QP + ks * 8 + t];
            unsigned a2 = sQ[r * QP + ks * 8 + t + 4];
            unsigned a3 = sQ[(r + 8) * QP + ks * 8 + t + 4];
#pragma unroll
            for (int nj = 0; nj < 8; nj++) {
                unsigned b0 = sKV[(nj * 8 + g) * KVP + ks * 8 + t];
                unsigned b1 = sKV[(nj * 8 + g) * KVP + ks * 8 + t + 4];
                mma_tf32(accs[nj], a0, a1, a2, a3, b0, b1);
            }
        }

        // online softmax (rows r0 = w*16+g, r1 = r0+8); quad shuffle reduce
        float rm0 = -1e30f, rm1 = -1e30f;
#pragma unroll
        for (int nj = 0; nj < 8; nj++) {
            rm0 = fmaxf(rm0, fmaxf(accs[nj][0], accs[nj][1]));
            rm1 = fmaxf(rm1, fmaxf(accs[nj][2], accs[nj][3]));
        }
        rm0 = fmaxf(rm0, __shfl_xor_sync(0xffffffffu, rm0, 1));
        rm0 = fmaxf(rm0, __shfl_xor_sync(0xffffffffu, rm0, 2));
        rm1 = fmaxf(rm1, __shfl_xor_sync(0xffffffffu, rm1, 1));
        rm1 = fmaxf(rm1, __shfl_xor_sync(0xffffffffu, rm1, 2));

        float nm0 = fmaxf(m0, rm0), nm1 = fmaxf(m1, rm1);
        float al0 = __expf(m0 - nm0), al1 = __expf(m1 - nm1);
        m0 = nm0; m1 = nm1;

        float sum0 = 0.f, sum1 = 0.f;
        int r0 = w * 16 + g;
#pragma unroll
        for (int nj = 0; nj < 8; nj++) {
            float p0 = __expf(accs[nj][0] - nm0);
            float p1 = __expf(accs[nj][1] - nm0);
            float p2 = __expf(accs[nj][2] - nm1);
            float p3 = __expf(accs[nj][3] - nm1);
            sum0 += p0 + p1;
            sum1 += p2 + p3;
            int c = nj * 8 + t * 2;
            sP[r0 * PP + c]     = f2tf32(p0);
            sP[r0 * PP + c + 1] = f2tf32(p1);
            sP[(r0 + 8) * PP + c]     = f2tf32(p2);
            sP[(r0 + 8) * PP + c + 1] = f2tf32(p3);
        }
        sum0 += __shfl_xor_sync(0xffffffffu, sum0, 1);
        sum0 += __shfl_xor_sync(0xffffffffu, sum0, 2);
        sum1 += __shfl_xor_sync(0xffffffffu, sum1, 1);
        sum1 += __shfl_xor_sync(0xffffffffu, sum1, 2);
        l0 = l0 * al0 + sum0;
        l1 = l1 * al1 + sum1;

#pragma unroll
        for (int nj = 0; nj < 16; nj++) {
            acc_o[nj][0] *= al0; acc_o[nj][1] *= al0;
            acc_o[nj][2] *= al1; acc_o[nj][3] *= al1;
        }
        __syncthreads();   // P written; K reads complete

        // load V chunk into same buffer
#pragma unroll
        for (int l = 0; l < 8; l++) {
            int i = tid + l * 256;
            int r = i >> 5, c = (i & 31) * 4;
            float4 vv = *(const float4*)&vb[(size_t)(s0 + r) * D_ + c];
            sKV[r * KVP + c + 0] = f2tf32(vv.x);
            sKV[r * KVP + c + 1] = f2tf32(vv.y);
            sKV[r * KVP + c + 2] = f2tf32(vv.z);
            sKV[r * KVP + c + 3] = f2tf32(vv.w);
        }
        __syncthreads();

        // O += P V   (warp: 16 q-rows x 128 d)
#pragma unroll
        for (int ks = 0; ks < 8; ks++) {
            unsigned a0 = sP[(w * 16 + g) * PP + ks * 8 + t];
            unsigned a1 = sP[(w * 16 + g + 8) * PP + ks * 8 + t];
            unsigned a2 = sP[(w * 16 + g) * PP + ks * 8 + t + 4];
            unsigned a3 = sP[(w * 16 + g + 8) * PP + ks * 8 + t + 4];
#pragma unroll
            for (int nj = 0; nj < 16; nj++) {
                unsigned b0 = sKV[(ks * 8 + t) * KVP + nj * 8 + g];
                unsigned b1 = sKV[(ks * 8 + t + 4) * KVP + nj * 8 + g];
                mma_tf32(acc_o[nj], a0, a1, a2, a3, b0, b1);
            }
        }
        __syncthreads();   // V reads done before next K load
    }

    // epilogue: normalize, write row-major [NTOK, E]
    float inv0 = 1.f / l0, inv1 = 1.f / l1;
    int row = b * T_ + qt * 128 + w * 16 + g;
#pragma unroll
    for (int nj = 0; nj < 16; nj++) {
        int col = h * D_ + nj * 8 + t * 2;
        float2 v0 = { acc_o[nj][0] * inv0, acc_o[nj][1] * inv0 };
        float2 v1 = { acc_o[nj][2] * inv1, acc_o[nj][3] * inv1 };
        *(float2*)&g_attn[(size_t)row * E_ + col]       = v0;
        *(float2*)&g_attn[(size_t)(row + 8) * E_ + col] = v1;
    }
}

// ---------------------------------------------------------------------------
extern "C" void kernel_launch(void* const* d_in, const int* in_sizes, int n_in,
                              void* d_out, int out_size)
{
    const float* x      = (const float*)d_in[0];
    const float* past_k = (const float*)d_in[1];
    const float* past_v = (const float*)d_in[2];
    const float* Wq     = (const float*)d_in[3];
    const float* bq     = (const float*)d_in[4];
    const float* Wk     = (const float*)d_in[5];
    const float* bk     = (const float*)d_in[6];
    const float* Wv     = (const float*)d_in[7];
    const float* bv     = (const float*)d_in[8];
    const float* Wo     = (const float*)d_in[9];
    const float* bo     = (const float*)d_in[10];

    float* out = (float*)d_out;                       // [B,T,E]
    float* kc  = out + (size_t)NTOK * E_;             // [B,H,S,D]
    float* vc  = kc + (size_t)B_ * H_ * S_ * D_;      // [B,H,S,D]

    void *pq, *pk, *pv, *pattn;
    cudaGetSymbolAddress(&pq, g_q);
    cudaGetSymbolAddress(&pk, g_k);
    cudaGetSymbolAddress(&pv, g_v);
    cudaGetSymbolAddress(&pattn, g_attn);

    dim3 gg(E_ / 128, NTOK / 128);   // (16, 32)
    gemm_tc<<<gg, 256>>>(x, Wq, bq, (float*)pq);
    gemm_tc<<<gg, 256>>>(x, Wk, bk, (float*)pk);
    gemm_tc<<<gg, 256>>>(x, Wv, bv, (float*)pv);

    {
        int total4 = NTOK * E_ / 4;
        scatter_kv<<<(total4 + 255) / 256, 256>>>((const float*)pk, (const float*)pv, kc, vc);
    }
    {
        int total4 = B_ * H_ * TP_ * D_ / 4;
        copy_past<<<(total4 + 255) / 256, 256>>>(past_k, past_v, kc, vc);
    }

    // attention
    size_t smem = (size_t)(128 * QP + 64 * KVP + 128 * PP) * sizeof(unsigned);
    cudaFuncSetAttribute(attn_tc, cudaFuncAttributeMaxDynamicSharedMemorySize, (int)smem);
    attn_tc<<<dim3(T_ / 128, H_, B_), 256, smem>>>(kc, vc);

    // output projection
    gemm_tc<<<gg, 256>>>((const float*)pattn, Wo, bo, out);
}